// round 11
// baseline (speedup 1.0000x reference)
#include <cuda_runtime.h>
#include <cstdint>

#define BATCH 8
#define CH    128
#define NP    4096
#define KNN   9
#define TK    16

#define NEG_INF __int_as_float(0xff800000)

// ---------------- scratch (static __device__, no allocs) ----------------
__device__ float g_sq[BATCH * NP];
__device__ float g_pd[(size_t)BATCH * NP * NP];            // 512 MB
__device__ float g_tm[(size_t)BATCH * NP * 32];            // per-(row, col-tile) max, 4 MB
__device__ int   g_idx[BATCH * NP * KNN];
__device__ float g_wT[CH * 512];                           // [c][r] combined conv1 weights (transposed)
__device__ float g_w2t[384 * CH];                          // [kk][o2] conv2 weights (transposed, kk=j*128+c)
__device__ float g_out1[(size_t)BATCH * NP * 512];         // [b][n][r]: r<128 -> y0, r=128+128t+o -> z_t
__device__ float g_h[(size_t)BATCH * NP * 3 * CH];         // [b][n][j][c]
__device__ float g_u[(size_t)BATCH * CH * NP];             // [b][o][n] conv2 pre-BN
__device__ float g_sum1[CH], g_ss1[CH], g_a1[CH], g_c1[CH];
__device__ float g_a2[CH], g_c2[CH];

// ---------------- K0: weight prep + zero stats ----------------
__global__ void prep_kernel(const float* __restrict__ w1, const float* __restrict__ w2) {
    int i = blockIdx.x * blockDim.x + threadIdx.x;
    if (i < CH * 512) {
        int c = i / 512, r = i % 512;
        float v;
        if (r < CH) {
            int o = r;
            v = 0.f;
            #pragma unroll
            for (int t = 0; t < 3; t++)
                v += w1[o * 768 + c * 3 + t] + w1[o * 768 + (CH + c) * 3 + t];
        } else {
            int t = (r - CH) >> 7, o = (r - CH) & 127;
            v = w1[o * 768 + (CH + c) * 3 + t];
        }
        g_wT[i] = v;
    }
    if (i < 384 * CH) {
        int kk = i / CH, o2 = i % CH;
        int j = kk >> 7, c = kk & 127;
        g_w2t[i] = w2[o2 * 384 + c * 3 + j];
    }
    if (i < CH) { g_sum1[i] = 0.f; g_ss1[i] = 0.f; }
}

// ---------------- K1: squared norms (double accumulation of fp32 squares) ----------------
__global__ void sq_kernel(const float* __restrict__ x) {
    int i = blockIdx.x * blockDim.x + threadIdx.x;   // i = b*NP + n
    if (i >= BATCH * NP) return;
    int b = i >> 12, n = i & (NP - 1);
    const float* xp = x + (size_t)b * CH * NP + n;
    double s = 0.0;
    #pragma unroll 8
    for (int c = 0; c < CH; c++) {
        float v = xp[(size_t)c * NP];
        float p = __fmul_rn(v, v);        // match ref: fp32-rounded squares
        s += (double)p;                    // exact-ish sum
    }
    g_sq[i] = (float)s;
}

// ---------------- K2: pairwise pd (symmetric tiled sgemm, cascaded accumulation)
//                  + per-(row, tile) max emission for topk tile skipping ----------------
__global__ __launch_bounds__(256) void pd_kernel(const float* __restrict__ x) {
    // triangular block decode: only bi <= bj tiles exist
    int u = blockIdx.x, b = blockIdx.z;
    int bj = (int)((sqrtf(8.f * (float)u + 1.f) - 1.f) * 0.5f);
    while ((bj + 1) * (bj + 2) / 2 <= u) bj++;
    while (bj * (bj + 1) / 2 > u) bj--;
    int bi = u - bj * (bj + 1) / 2;

    __shared__ float As[TK][132];
    __shared__ float Bs[TK][132];
    __shared__ float Ms[128][17];     // mirror-row partial maxes [row][ty]
    const float* xb = x + (size_t)b * CH * NP;
    int n0 = bi * 128, m0 = bj * 128;
    int t = threadIdx.x, tx = t & 15, ty = t >> 4;

    float acc[8][8];
    #pragma unroll
    for (int i = 0; i < 8; i++)
        #pragma unroll
        for (int j = 0; j < 8; j++) acc[i][j] = 0.f;

    for (int k0 = 0; k0 < CH; k0 += TK) {
        #pragma unroll
        for (int q = 0; q < 2; q++) {
            int qq = t + q * 256;             // 0..511
            int kc = qq >> 5, c4 = (qq & 31) << 2;
            float4 va = *(const float4*)&xb[(size_t)(k0 + kc) * NP + n0 + c4];
            float4 vb = *(const float4*)&xb[(size_t)(k0 + kc) * NP + m0 + c4];
            *(float4*)&As[kc][c4] = va;
            *(float4*)&Bs[kc][c4] = vb;
        }
        __syncthreads();
        // fresh chunk accumulators: keeps partial-sum magnitudes small
        float accC[8][8];
        #pragma unroll
        for (int i = 0; i < 8; i++)
            #pragma unroll
            for (int j = 0; j < 8; j++) accC[i][j] = 0.f;
        #pragma unroll
        for (int k = 0; k < TK; k++) {
            float a[8], bb[8];
            *(float4*)(a)      = *(float4*)&As[k][ty * 4];
            *(float4*)(a + 4)  = *(float4*)&As[k][ty * 4 + 64];
            *(float4*)(bb)     = *(float4*)&Bs[k][tx * 4];
            *(float4*)(bb + 4) = *(float4*)&Bs[k][tx * 4 + 64];
            #pragma unroll
            for (int i = 0; i < 8; i++)
                #pragma unroll
                for (int j = 0; j < 8; j++)
                    accC[i][j] = fmaf(a[i], bb[j], accC[i][j]);
        }
        #pragma unroll
        for (int i = 0; i < 8; i++)
            #pragma unroll
            for (int j = 0; j < 8; j++)
                acc[i][j] = __fadd_rn(acc[i][j], accC[i][j]);
        __syncthreads();
    }

    float sqn[8], sqm[8];
    #pragma unroll
    for (int i = 0; i < 8; i++)
        sqn[i] = g_sq[b * NP + n0 + ty * 4 + (i & 3) + ((i >> 2) << 6)];
    #pragma unroll
    for (int j = 0; j < 8; j++)
        sqm[j] = g_sq[b * NP + m0 + tx * 4 + (j & 3) + ((j >> 2) << 6)];

    float* pdb = g_pd + (size_t)b * NP * NP;
    // forward stores (rows n, coalesced float4) + per-row tile max
    #pragma unroll
    for (int i = 0; i < 8; i++) {
        int n = n0 + ty * 4 + (i & 3) + ((i >> 2) << 6);
        float v0[4], v1[4];
        #pragma unroll
        for (int e = 0; e < 4; e++) {
            float t0 = __fsub_rn(__fmul_rn(2.f, acc[i][e]),     sqn[i]); v0[e] = __fsub_rn(t0, sqm[e]);
            float t1 = __fsub_rn(__fmul_rn(2.f, acc[i][4 + e]), sqn[i]); v1[e] = __fsub_rn(t1, sqm[4 + e]);
        }
        *(float4*)&pdb[(size_t)n * NP + m0 + tx * 4]      = *(float4*)v0;
        *(float4*)&pdb[(size_t)n * NP + m0 + tx * 4 + 64] = *(float4*)v1;
        // row max over this thread's 8 cols, then across the 16 tx lanes (same half-warp)
        float rmax = fmaxf(fmaxf(fmaxf(v0[0], v0[1]), fmaxf(v0[2], v0[3])),
                           fmaxf(fmaxf(v1[0], v1[1]), fmaxf(v1[2], v1[3])));
        #pragma unroll
        for (int off = 8; off >= 1; off >>= 1)
            rmax = fmaxf(rmax, __shfl_xor_sync(0xffffffffu, rmax, off));
        if (tx == 0) g_tm[(size_t)(b * NP + n) * 32 + bj] = rmax;
    }
    // mirror stores (rows m): j-outer, i-inner, emit two float4 per m-row + tile max via smem
    if (bi != bj) {
        #pragma unroll
        for (int j = 0; j < 8; j++) {
            int jj = tx * 4 + (j & 3) + ((j >> 2) << 6);    // row-local index 0..127
            int m = m0 + jj;
            float w0[4], w1v[4];
            #pragma unroll
            for (int i = 0; i < 4; i++) {
                float t2 = __fsub_rn(__fmul_rn(2.f, acc[i][j]), sqm[j]);   // reference order for row m
                w0[i] = __fsub_rn(t2, sqn[i]);                              // n = n0+ty*4+i (consecutive)
            }
            #pragma unroll
            for (int i = 4; i < 8; i++) {
                float t2 = __fsub_rn(__fmul_rn(2.f, acc[i][j]), sqm[j]);
                w1v[i - 4] = __fsub_rn(t2, sqn[i]);                         // n = n0+ty*4+64+(i-4)
            }
            *(float4*)&pdb[(size_t)m * NP + n0 + ty * 4]      = *(float4*)w0;
            *(float4*)&pdb[(size_t)m * NP + n0 + ty * 4 + 64] = *(float4*)w1v;
            float mm = fmaxf(fmaxf(fmaxf(w0[0], w0[1]), fmaxf(w0[2], w0[3])),
                             fmaxf(fmaxf(w1v[0], w1v[1]), fmaxf(w1v[2], w1v[3])));
            Ms[jj][ty] = mm;
        }
        __syncthreads();
        if (t < 128) {
            float r = Ms[t][0];
            #pragma unroll
            for (int q = 1; q < 16; q++) r = fmaxf(r, Ms[t][q]);
            g_tm[(size_t)(b * NP + m0 + t) * 32 + bi] = r;
        }
    }
}

// ---------------- K3: top-9 per row via exact tile-max threshold (jax top_k semantics) ----------------
// v9 = 9th largest of the 32 tile maxima. The 9 selected maxima are 9 distinct
// elements >= v9, so any p < v9 can never be in the top-9 (even under jax's
// lower-index tie-break). Also v9 <= global-9th, so keeping p >= v9 retains all
// true top-9 elements and all value-ties. Expected: ~9 tiles scanned, ~11 inserts.
__global__ __launch_bounds__(256) void topk_kernel() {
    int warp = threadIdx.x >> 5, lane = threadIdx.x & 31;
    int row = blockIdx.x * 8 + warp;                 // row = b*NP + n
    const float4* pr = (const float4*)(g_pd + (size_t)row * NP);
    float tm = g_tm[(size_t)row * 32 + lane];        // lane's tile max

    // v9 = 9th largest of the 32 tile maxima (multiset order, 9 extraction rounds)
    float rem = tm, v9 = NEG_INF;
    #pragma unroll
    for (int r = 0; r < KNN; r++) {
        float m = rem;
        #pragma unroll
        for (int off = 16; off >= 1; off >>= 1)
            m = fmaxf(m, __shfl_xor_sync(0xffffffffu, m, off));
        v9 = m;
        unsigned msk = __ballot_sync(0xffffffffu, rem == m);
        int src = __ffs((int)msk) - 1;               // remove exactly one holder per round
        if (lane == src) rem = NEG_INF;
    }

    float v[KNN]; int id[KNN];
    #pragma unroll
    for (int s = 0; s < KNN; s++) { v[s] = NEG_INF; id[s] = 0x7fffffff; }

    for (int tt = 0; tt < 32; tt++) {
        float tmt = __shfl_sync(0xffffffffu, tm, tt);
        if (tmt >= v9) {                             // warp-uniform tile skip
            float4 p = pr[tt * 32 + lane];           // tile tt: 128 floats, one float4/lane
            float mx = fmaxf(fmaxf(p.x, p.y), fmaxf(p.z, p.w));
            if (mx >= v9) {
                int mbase = (tt * 32 + lane) * 4;
                float pe[4] = {p.x, p.y, p.z, p.w};
                #pragma unroll
                for (int e = 0; e < 4; e++) {
                    float cv = pe[e];
                    if (cv >= v9) {
                        int ci = mbase + e;
                        #pragma unroll
                        for (int s = 0; s < KNN; s++) {
                            bool take = (cv > v[s]);
                            float tv = take ? v[s] : cv;  int ti = take ? id[s] : ci;
                            v[s]  = take ? cv : v[s];     id[s] = take ? ci : id[s];
                            cv = tv; ci = ti;
                        }
                    }
                }
            }
        }
    }

    int* outp = g_idx + row * KNN;
    #pragma unroll
    for (int r = 0; r < KNN; r++) {
        float cv = v[0]; int ci = id[0];
        #pragma unroll
        for (int s = 1; s < KNN; s++) {
            bool better = (v[s] > cv) || (v[s] == cv && id[s] < ci);
            cv = better ? v[s] : cv; ci = better ? id[s] : ci;
        }
        #pragma unroll
        for (int off = 16; off >= 1; off >>= 1) {
            float wv = __shfl_xor_sync(0xffffffffu, cv, off);
            int   wi = __shfl_xor_sync(0xffffffffu, ci, off);
            bool better = (wv > cv) || (wv == cv && wi < ci);
            cv = better ? wv : cv; ci = better ? wi : ci;
        }
        if (lane == 0) outp[r] = ci;
        #pragma unroll
        for (int s = 0; s < KNN; s++)
            if (id[s] == ci) { v[s] = NEG_INF; id[s] = 0x7fffffff; }
    }
}

// ---------------- K4: combined conv1 GEMM: out1[b][n][r] = W[r][:] . x[:, n] ----------------
__global__ __launch_bounds__(256) void gemm1_kernel(const float* __restrict__ x) {
    __shared__ float As[TK][132];   // [k][r]
    __shared__ float Bs[TK][132];   // [k][n]
    int b = blockIdx.z, r0 = blockIdx.x * 128, n0 = blockIdx.y * 128;
    const float* xb = x + (size_t)b * CH * NP;
    int t = threadIdx.x, tx = t & 15, ty = t >> 4;

    float acc[8][8];
    #pragma unroll
    for (int i = 0; i < 8; i++)
        #pragma unroll
        for (int j = 0; j < 8; j++) acc[i][j] = 0.f;

    for (int k0 = 0; k0 < CH; k0 += TK) {
        #pragma unroll
        for (int q = 0; q < 2; q++) {
            int qq = t + q * 256;
            int kc = qq >> 5, c4 = (qq & 31) << 2;
            *(float4*)&As[kc][c4] = *(const float4*)&g_wT[(k0 + kc) * 512 + r0 + c4];
            *(float4*)&Bs[kc][c4] = *(const float4*)&xb[(size_t)(k0 + kc) * NP + n0 + c4];
        }
        __syncthreads();
        #pragma unroll
        for (int k = 0; k < TK; k++) {
            float fr[8], fn[8];
            *(float4*)(fr)     = *(float4*)&As[k][tx * 4];
            *(float4*)(fr + 4) = *(float4*)&As[k][tx * 4 + 64];
            *(float4*)(fn)     = *(float4*)&Bs[k][ty * 4];
            *(float4*)(fn + 4) = *(float4*)&Bs[k][ty * 4 + 64];
            #pragma unroll
            for (int i = 0; i < 8; i++)
                #pragma unroll
                for (int j = 0; j < 8; j++)
                    acc[i][j] = fmaf(fn[i], fr[j], acc[i][j]);
        }
        __syncthreads();
    }
    #pragma unroll
    for (int i = 0; i < 8; i++) {
        int n = n0 + ty * 4 + (i & 3) + ((i >> 2) << 6);
        float* op = g_out1 + (size_t)(b * NP + n) * 512 + r0;
        *(float4*)&op[tx * 4]      = *(float4*)&acc[i][0];
        *(float4*)&op[tx * 4 + 64] = *(float4*)&acc[i][4];
    }
}

// ---------------- K5: gather + edge combine + bn1 partial stats ----------------
__global__ __launch_bounds__(128) void gather_kernel(const float* __restrict__ b1) {
    int b = blockIdx.y, nbase = blockIdx.x * 32;
    int o = threadIdx.x;
    float b1o = b1[o];
    float s = 0.f, ss = 0.f;
    for (int nn = 0; nn < 32; nn++) {
        int n = nbase + nn;
        const int* ip = g_idx + (b * NP + n) * KNN;
        const float* base = g_out1 + (size_t)(b * NP + n) * 512;
        float y0 = base[o] + b1o;
        float* hp = g_h + (size_t)(b * NP + n) * 3 * CH + o;
        #pragma unroll
        for (int j = 0; j < 3; j++) {
            int m0 = ip[j * 3 + 0], m1 = ip[j * 3 + 1], m2 = ip[j * 3 + 2];
            float z0 = g_out1[(size_t)(b * NP + m0) * 512 + 128 + o];
            float z1 = g_out1[(size_t)(b * NP + m1) * 512 + 256 + o];
            float z2 = g_out1[(size_t)(b * NP + m2) * 512 + 384 + o];
            float hv = y0 - z0 - z1 - z2;
            hp[j * CH] = hv;
            s += hv; ss = fmaf(hv, hv, ss);
        }
    }
    atomicAdd(&g_sum1[o], s);
    atomicAdd(&g_ss1[o], ss);
}

// ---------------- K6: finalize bn1 affine ----------------
__global__ void fin1_kernel(const float* __restrict__ g1, const float* __restrict__ beta1) {
    int o = threadIdx.x;
    float cnt = (float)(BATCH * NP * 3);
    float m = g_sum1[o] / cnt;
    float var = g_ss1[o] / cnt - m * m;
    var = fmaxf(var, 0.f);
    float is = rsqrtf(var + 1e-5f);
    float a = g1[o] * is;
    g_a1[o] = a;
    g_c1[o] = beta1[o] - m * a;
}

// ---------------- K7: conv2 GEMM with fused bn1-affine+relu on B load ----------------
__global__ __launch_bounds__(256) void gemm2_kernel(const float* __restrict__ b2) {
    __shared__ float As[TK][132];   // [k][o2]
    __shared__ float Bs[TK][132];   // [k][n]
    __shared__ float s_a1[CH], s_c1[CH];
    int b = blockIdx.y, n0 = blockIdx.x * 128;
    int t = threadIdx.x, tx = t & 15, ty = t >> 4;
    if (t < CH) { s_a1[t] = g_a1[t]; s_c1[t] = g_c1[t]; }
    __syncthreads();

    float acc[8][8];
    #pragma unroll
    for (int i = 0; i < 8; i++)
        #pragma unroll
        for (int j = 0; j < 8; j++) acc[i][j] = 0.f;

    for (int k0 = 0; k0 < 384; k0 += TK) {
        #pragma unroll
        for (int q = 0; q < 2; q++) {
            int qq = t + q * 256;
            int kc = qq >> 5, c4 = (qq & 31) << 2;
            *(float4*)&As[kc][c4] = *(const float4*)&g_w2t[(k0 + kc) * CH + c4];
        }
        #pragma unroll
        for (int q = 0; q < 2; q++) {
            int qq = t + q * 256;                 // 0..511
            int n_l = qq >> 2, kq = (qq & 3) << 2;
            float4 hv = *(const float4*)&g_h[(size_t)(b * NP + n0 + n_l) * 384 + k0 + kq];
            float vv[4] = {hv.x, hv.y, hv.z, hv.w};
            #pragma unroll
            for (int e = 0; e < 4; e++) {
                int c = (k0 + kq + e) & 127;
                Bs[kq + e][n_l] = fmaxf(fmaf(vv[e], s_a1[c], s_c1[c]), 0.f);
            }
        }
        __syncthreads();
        #pragma unroll
        for (int k = 0; k < TK; k++) {
            float fo[8], fn[8];
            *(float4*)(fo)     = *(float4*)&As[k][ty * 4];
            *(float4*)(fo + 4) = *(float4*)&As[k][ty * 4 + 64];
            *(float4*)(fn)     = *(float4*)&Bs[k][tx * 4];
            *(float4*)(fn + 4) = *(float4*)&Bs[k][tx * 4 + 64];
            #pragma unroll
            for (int i = 0; i < 8; i++)
                #pragma unroll
                for (int j = 0; j < 8; j++)
                    acc[i][j] = fmaf(fo[i], fn[j], acc[i][j]);
        }
        __syncthreads();
    }
    #pragma unroll
    for (int i = 0; i < 8; i++) {
        int o2 = ty * 4 + (i & 3) + ((i >> 2) << 6);
        float bb = b2[o2];
        float v0[4], v1[4];
        #pragma unroll
        for (int e = 0; e < 4; e++) { v0[e] = acc[i][e] + bb; v1[e] = acc[i][4 + e] + bb; }
        float* up = g_u + (size_t)(b * CH + o2) * NP + n0;
        *(float4*)&up[tx * 4]      = *(float4*)v0;
        *(float4*)&up[tx * 4 + 64] = *(float4*)v1;
    }
}

// ---------------- K8: bn2 stats + affine (block per channel) ----------------
__global__ __launch_bounds__(256) void stats2_kernel(const float* __restrict__ g2, const float* __restrict__ beta2) {
    int o2 = blockIdx.x;
    int t = threadIdx.x;
    float s = 0.f, ss = 0.f;
    for (int b = 0; b < BATCH; b++) {
        const float* up = g_u + (size_t)(b * CH + o2) * NP;
        for (int n = t; n < NP; n += 256) {
            float v = up[n];
            s += v; ss = fmaf(v, v, ss);
        }
    }
    __shared__ float rs[256], rss[256];
    rs[t] = s; rss[t] = ss;
    __syncthreads();
    for (int off = 128; off >= 1; off >>= 1) {
        if (t < off) { rs[t] += rs[t + off]; rss[t] += rss[t + off]; }
        __syncthreads();
    }
    if (t == 0) {
        float cnt = (float)(BATCH * NP);
        float m = rs[0] / cnt;
        float var = rss[0] / cnt - m * m;
        var = fmaxf(var, 0.f);
        float is = rsqrtf(var + 1e-5f);
        float a = g2[o2] * is;
        g_a2[o2] = a;
        g_c2[o2] = beta2[o2] - m * a;
    }
}

// ---------------- K9: final elementwise bn2+relu to output (float4) ----------------
__global__ void out_kernel(float* __restrict__ out) {
    int i = blockIdx.x * blockDim.x + threadIdx.x;    // float4 index
    if (i >= (BATCH * CH * NP) / 4) return;
    int o = (i >> 10) & 127;                          // (i*4 >> 12) & 127
    float a = g_a2[o], c = g_c2[o];
    float4 u = *((const float4*)g_u + i);
    float4 r;
    r.x = fmaxf(fmaf(u.x, a, c), 0.f);
    r.y = fmaxf(fmaf(u.y, a, c), 0.f);
    r.z = fmaxf(fmaf(u.z, a, c), 0.f);
    r.w = fmaxf(fmaf(u.w, a, c), 0.f);
    *((float4*)out + i) = r;
}

// ---------------- launch ----------------
extern "C" void kernel_launch(void* const* d_in, const int* in_sizes, int n_in,
                              void* d_out, int out_size) {
    const float* x     = (const float*)d_in[0];
    const float* w1    = (const float*)d_in[1];
    const float* b1    = (const float*)d_in[2];
    const float* g1    = (const float*)d_in[3];
    const float* beta1 = (const float*)d_in[4];
    const float* w2    = (const float*)d_in[5];
    const float* b2    = (const float*)d_in[6];
    const float* g2    = (const float*)d_in[7];
    const float* beta2 = (const float*)d_in[8];
    float* out = (float*)d_out;

    prep_kernel<<<256, 256>>>(w1, w2);
    sq_kernel<<<(BATCH * NP) / 256, 256>>>(x);
    pd_kernel<<<dim3(528, 1, BATCH), 256>>>(x);
    topk_kernel<<<(BATCH * NP) / 8, 256>>>();
    gemm1_kernel<<<dim3(4, 32, BATCH), 256>>>(x);
    gather_kernel<<<dim3(128, BATCH), 128>>>(b1);
    fin1_kernel<<<1, 128>>>(g1, beta1);
    gemm2_kernel<<<dim3(32, BATCH), 256>>>(b2);
    stats2_kernel<<<128, 256>>>(g2, beta2);
    out_kernel<<<(BATCH * CH * NP / 4 + 255) / 256, 256>>>(out);
}

// round 15
// speedup vs baseline: 1.5266x; 1.5266x over previous
#include <cuda_runtime.h>
#include <cstdint>

#define BATCH 8
#define CH    128
#define NP    4096
#define KNN   9
#define TK    16

#define NEG_INF __int_as_float(0xff800000)

// ---------------- scratch (static __device__, no allocs) ----------------
__device__ float g_sq[BATCH * NP];
__device__ float g_pd[(size_t)BATCH * NP * NP];            // 512 MB
__device__ float g_tm[(size_t)BATCH * NP * 32];            // per-(row, col-tile) max, 4 MB
__device__ int   g_idx[BATCH * NP * KNN];
__device__ float g_wT[CH * 512];                           // [c][r] combined conv1 weights (transposed)
__device__ float g_w2t[384 * CH];                          // [kk][o2] conv2 weights (transposed, kk=j*128+c)
__device__ float g_out1[(size_t)BATCH * NP * 512];         // [b][n][r]: r<128 -> y0, r=128+128t+o -> z_t
__device__ float g_h[(size_t)BATCH * NP * 3 * CH];         // [b][n][j][c]
__device__ float g_u[(size_t)BATCH * CH * NP];             // [b][o][n] conv2 pre-BN
__device__ float g_sum1[CH], g_ss1[CH], g_a1[CH], g_c1[CH];
__device__ float g_a2[CH], g_c2[CH];

// ---------------- K0: weight prep + zero stats ----------------
__global__ void prep_kernel(const float* __restrict__ w1, const float* __restrict__ w2) {
    int i = blockIdx.x * blockDim.x + threadIdx.x;
    if (i < CH * 512) {
        int c = i / 512, r = i % 512;
        float v;
        if (r < CH) {
            int o = r;
            v = 0.f;
            #pragma unroll
            for (int t = 0; t < 3; t++)
                v += w1[o * 768 + c * 3 + t] + w1[o * 768 + (CH + c) * 3 + t];
        } else {
            int t = (r - CH) >> 7, o = (r - CH) & 127;
            v = w1[o * 768 + (CH + c) * 3 + t];
        }
        g_wT[i] = v;
    }
    if (i < 384 * CH) {
        int kk = i / CH, o2 = i % CH;
        int j = kk >> 7, c = kk & 127;
        g_w2t[i] = w2[o2 * 384 + c * 3 + j];
    }
    if (i < CH) { g_sum1[i] = 0.f; g_ss1[i] = 0.f; }
}

// ---------------- K1: squared norms (double accumulation of fp32 squares) ----------------
__global__ void sq_kernel(const float* __restrict__ x) {
    int i = blockIdx.x * blockDim.x + threadIdx.x;   // i = b*NP + n
    if (i >= BATCH * NP) return;
    int b = i >> 12, n = i & (NP - 1);
    const float* xp = x + (size_t)b * CH * NP + n;
    double s = 0.0;
    #pragma unroll 8
    for (int c = 0; c < CH; c++) {
        float v = xp[(size_t)c * NP];
        float p = __fmul_rn(v, v);        // match ref: fp32-rounded squares
        s += (double)p;                    // exact-ish sum
    }
    g_sq[i] = (float)s;
}

// ---------------- K2: pairwise pd (symmetric tiled sgemm, cascaded accumulation,
//                  register-prefetch software pipeline) + per-(row, tile) max ----------------
__global__ __launch_bounds__(256) void pd_kernel(const float* __restrict__ x) {
    // triangular block decode: only bi <= bj tiles exist
    int u = blockIdx.x, b = blockIdx.z;
    int bj = (int)((sqrtf(8.f * (float)u + 1.f) - 1.f) * 0.5f);
    while ((bj + 1) * (bj + 2) / 2 <= u) bj++;
    while (bj * (bj + 1) / 2 > u) bj--;
    int bi = u - bj * (bj + 1) / 2;

    __shared__ float As[TK][132];
    __shared__ float Bs[TK][132];
    __shared__ float Ms[128][17];     // mirror-row partial maxes [row][ty]
    const float* xb = x + (size_t)b * CH * NP;
    int n0 = bi * 128, m0 = bj * 128;
    int t = threadIdx.x, tx = t & 15, ty = t >> 4;

    // per-thread load coordinates (2 float4 loads per chunk)
    int kc0 = t >> 5,        c40 = (t & 31) << 2;
    int kc1 = (t + 256) >> 5, c41 = ((t + 256) & 31) << 2;

    float acc[8][8];
    #pragma unroll
    for (int i = 0; i < 8; i++)
        #pragma unroll
        for (int j = 0; j < 8; j++) acc[i][j] = 0.f;

    // prefetch chunk 0 into registers
    float4 ra0 = *(const float4*)&xb[(size_t)kc0 * NP + n0 + c40];
    float4 rb0 = *(const float4*)&xb[(size_t)kc0 * NP + m0 + c40];
    float4 ra1 = *(const float4*)&xb[(size_t)kc1 * NP + n0 + c41];
    float4 rb1 = *(const float4*)&xb[(size_t)kc1 * NP + m0 + c41];

    for (int k0 = 0; k0 < CH; k0 += TK) {
        __syncthreads();                 // smem free (previous compute done)
        *(float4*)&As[kc0][c40] = ra0;
        *(float4*)&Bs[kc0][c40] = rb0;
        *(float4*)&As[kc1][c41] = ra1;
        *(float4*)&Bs[kc1][c41] = rb1;
        __syncthreads();
        if (k0 + TK < CH) {              // prefetch next chunk (overlaps compute)
            ra0 = *(const float4*)&xb[(size_t)(k0 + TK + kc0) * NP + n0 + c40];
            rb0 = *(const float4*)&xb[(size_t)(k0 + TK + kc0) * NP + m0 + c40];
            ra1 = *(const float4*)&xb[(size_t)(k0 + TK + kc1) * NP + n0 + c41];
            rb1 = *(const float4*)&xb[(size_t)(k0 + TK + kc1) * NP + m0 + c41];
        }
        // fresh chunk accumulators: keeps partial-sum magnitudes small
        float accC[8][8];
        #pragma unroll
        for (int i = 0; i < 8; i++)
            #pragma unroll
            for (int j = 0; j < 8; j++) accC[i][j] = 0.f;
        #pragma unroll
        for (int k = 0; k < TK; k++) {
            float a[8], bb[8];
            *(float4*)(a)      = *(float4*)&As[k][ty * 4];
            *(float4*)(a + 4)  = *(float4*)&As[k][ty * 4 + 64];
            *(float4*)(bb)     = *(float4*)&Bs[k][tx * 4];
            *(float4*)(bb + 4) = *(float4*)&Bs[k][tx * 4 + 64];
            #pragma unroll
            for (int i = 0; i < 8; i++)
                #pragma unroll
                for (int j = 0; j < 8; j++)
                    accC[i][j] = fmaf(a[i], bb[j], accC[i][j]);
        }
        #pragma unroll
        for (int i = 0; i < 8; i++)
            #pragma unroll
            for (int j = 0; j < 8; j++)
                acc[i][j] = __fadd_rn(acc[i][j], accC[i][j]);
    }

    float sqn[8], sqm[8];
    #pragma unroll
    for (int i = 0; i < 8; i++)
        sqn[i] = g_sq[b * NP + n0 + ty * 4 + (i & 3) + ((i >> 2) << 6)];
    #pragma unroll
    for (int j = 0; j < 8; j++)
        sqm[j] = g_sq[b * NP + m0 + tx * 4 + (j & 3) + ((j >> 2) << 6)];

    float* pdb = g_pd + (size_t)b * NP * NP;
    // forward stores (rows n, coalesced float4) + per-row tile max
    #pragma unroll
    for (int i = 0; i < 8; i++) {
        int n = n0 + ty * 4 + (i & 3) + ((i >> 2) << 6);
        float v0[4], v1[4];
        #pragma unroll
        for (int e = 0; e < 4; e++) {
            float t0 = __fsub_rn(__fmul_rn(2.f, acc[i][e]),     sqn[i]); v0[e] = __fsub_rn(t0, sqm[e]);
            float t1 = __fsub_rn(__fmul_rn(2.f, acc[i][4 + e]), sqn[i]); v1[e] = __fsub_rn(t1, sqm[4 + e]);
        }
        *(float4*)&pdb[(size_t)n * NP + m0 + tx * 4]      = *(float4*)v0;
        *(float4*)&pdb[(size_t)n * NP + m0 + tx * 4 + 64] = *(float4*)v1;
        // row max over this thread's 8 cols, then across the 16 tx lanes (same half-warp)
        float rmax = fmaxf(fmaxf(fmaxf(v0[0], v0[1]), fmaxf(v0[2], v0[3])),
                           fmaxf(fmaxf(v1[0], v1[1]), fmaxf(v1[2], v1[3])));
        #pragma unroll
        for (int off = 8; off >= 1; off >>= 1)
            rmax = fmaxf(rmax, __shfl_xor_sync(0xffffffffu, rmax, off));
        if (tx == 0) g_tm[(size_t)(b * NP + n) * 32 + bj] = rmax;
    }
    // mirror stores (rows m): j-outer, i-inner, emit two float4 per m-row + tile max via smem
    if (bi != bj) {
        __syncthreads();                  // Ms reuses smem timeline; ensure prior phase done
        #pragma unroll
        for (int j = 0; j < 8; j++) {
            int jj = tx * 4 + (j & 3) + ((j >> 2) << 6);    // row-local index 0..127
            int m = m0 + jj;
            float w0[4], w1v[4];
            #pragma unroll
            for (int i = 0; i < 4; i++) {
                float t2 = __fsub_rn(__fmul_rn(2.f, acc[i][j]), sqm[j]);   // reference order for row m
                w0[i] = __fsub_rn(t2, sqn[i]);                              // n = n0+ty*4+i (consecutive)
            }
            #pragma unroll
            for (int i = 4; i < 8; i++) {
                float t2 = __fsub_rn(__fmul_rn(2.f, acc[i][j]), sqm[j]);
                w1v[i - 4] = __fsub_rn(t2, sqn[i]);                         // n = n0+ty*4+64+(i-4)
            }
            *(float4*)&pdb[(size_t)m * NP + n0 + ty * 4]      = *(float4*)w0;
            *(float4*)&pdb[(size_t)m * NP + n0 + ty * 4 + 64] = *(float4*)w1v;
            float mm = fmaxf(fmaxf(fmaxf(w0[0], w0[1]), fmaxf(w0[2], w0[3])),
                             fmaxf(fmaxf(w1v[0], w1v[1]), fmaxf(w1v[2], w1v[3])));
            Ms[jj][ty] = mm;
        }
        __syncthreads();
        if (t < 128) {
            float r = Ms[t][0];
            #pragma unroll
            for (int q = 1; q < 16; q++) r = fmaxf(r, Ms[t][q]);
            g_tm[(size_t)(b * NP + m0 + t) * 32 + bi] = r;
        }
    }
}

// ---------------- K3: top-9 per row via exact tile-max threshold (jax top_k semantics) ----------------
// v9 = 9th largest of the 32 tile maxima. The 9 selected maxima are 9 distinct
// elements >= v9, so any p < v9 can never be in the top-9 (even under jax's
// lower-index tie-break). Also v9 <= global-9th, so keeping p >= v9 retains all
// true top-9 elements and all value-ties. Expected: ~9 tiles scanned, ~11 inserts.
__global__ __launch_bounds__(256) void topk_kernel() {
    int warp = threadIdx.x >> 5, lane = threadIdx.x & 31;
    int row = blockIdx.x * 8 + warp;                 // row = b*NP + n
    const float4* pr = (const float4*)(g_pd + (size_t)row * NP);
    float tm = g_tm[(size_t)row * 32 + lane];        // lane's tile max

    // v9 = 9th largest of the 32 tile maxima (multiset order, 9 extraction rounds)
    float rem = tm, v9 = NEG_INF;
    #pragma unroll
    for (int r = 0; r < KNN; r++) {
        float m = rem;
        #pragma unroll
        for (int off = 16; off >= 1; off >>= 1)
            m = fmaxf(m, __shfl_xor_sync(0xffffffffu, m, off));
        v9 = m;
        unsigned msk = __ballot_sync(0xffffffffu, rem == m);
        int src = __ffs((int)msk) - 1;               // remove exactly one holder per round
        if (lane == src) rem = NEG_INF;
    }

    float v[KNN]; int id[KNN];
    #pragma unroll
    for (int s = 0; s < KNN; s++) { v[s] = NEG_INF; id[s] = 0x7fffffff; }

    for (int tt = 0; tt < 32; tt++) {
        float tmt = __shfl_sync(0xffffffffu, tm, tt);
        if (tmt >= v9) {                             // warp-uniform tile skip
            float4 p = pr[tt * 32 + lane];           // tile tt: 128 floats, one float4/lane
            float mx = fmaxf(fmaxf(p.x, p.y), fmaxf(p.z, p.w));
            if (mx >= v9) {
                int mbase = (tt * 32 + lane) * 4;
                float pe[4] = {p.x, p.y, p.z, p.w};
                #pragma unroll
                for (int e = 0; e < 4; e++) {
                    float cv = pe[e];
                    if (cv >= v9) {
                        int ci = mbase + e;
                        #pragma unroll
                        for (int s = 0; s < KNN; s++) {
                            bool take = (cv > v[s]);
                            float tv = take ? v[s] : cv;  int ti = take ? id[s] : ci;
                            v[s]  = take ? cv : v[s];     id[s] = take ? ci : id[s];
                            cv = tv; ci = ti;
                        }
                    }
                }
            }
        }
    }

    int* outp = g_idx + row * KNN;
    #pragma unroll
    for (int r = 0; r < KNN; r++) {
        float cv = v[0]; int ci = id[0];
        #pragma unroll
        for (int s = 1; s < KNN; s++) {
            bool better = (v[s] > cv) || (v[s] == cv && id[s] < ci);
            cv = better ? v[s] : cv; ci = better ? id[s] : ci;
        }
        #pragma unroll
        for (int off = 16; off >= 1; off >>= 1) {
            float wv = __shfl_xor_sync(0xffffffffu, cv, off);
            int   wi = __shfl_xor_sync(0xffffffffu, ci, off);
            bool better = (wv > cv) || (wv == cv && wi < ci);
            cv = better ? wv : cv; ci = better ? wi : ci;
        }
        if (lane == 0) outp[r] = ci;
        #pragma unroll
        for (int s = 0; s < KNN; s++)
            if (id[s] == ci) { v[s] = NEG_INF; id[s] = 0x7fffffff; }
    }
}

// ---------------- K4: combined conv1 GEMM: out1[b][n][r] = W[r][:] . x[:, n] ----------------
__global__ __launch_bounds__(256) void gemm1_kernel(const float* __restrict__ x) {
    __shared__ float As[TK][132];   // [k][r]
    __shared__ float Bs[TK][132];   // [k][n]
    int b = blockIdx.z, r0 = blockIdx.x * 128, n0 = blockIdx.y * 128;
    const float* xb = x + (size_t)b * CH * NP;
    int t = threadIdx.x, tx = t & 15, ty = t >> 4;

    float acc[8][8];
    #pragma unroll
    for (int i = 0; i < 8; i++)
        #pragma unroll
        for (int j = 0; j < 8; j++) acc[i][j] = 0.f;

    for (int k0 = 0; k0 < CH; k0 += TK) {
        #pragma unroll
        for (int q = 0; q < 2; q++) {
            int qq = t + q * 256;
            int kc = qq >> 5, c4 = (qq & 31) << 2;
            *(float4*)&As[kc][c4] = *(const float4*)&g_wT[(k0 + kc) * 512 + r0 + c4];
            *(float4*)&Bs[kc][c4] = *(const float4*)&xb[(size_t)(k0 + kc) * NP + n0 + c4];
        }
        __syncthreads();
        #pragma unroll
        for (int k = 0; k < TK; k++) {
            float fr[8], fn[8];
            *(float4*)(fr)     = *(float4*)&As[k][tx * 4];
            *(float4*)(fr + 4) = *(float4*)&As[k][tx * 4 + 64];
            *(float4*)(fn)     = *(float4*)&Bs[k][ty * 4];
            *(float4*)(fn + 4) = *(float4*)&Bs[k][ty * 4 + 64];
            #pragma unroll
            for (int i = 0; i < 8; i++)
                #pragma unroll
                for (int j = 0; j < 8; j++)
                    acc[i][j] = fmaf(fn[i], fr[j], acc[i][j]);
        }
        __syncthreads();
    }
    #pragma unroll
    for (int i = 0; i < 8; i++) {
        int n = n0 + ty * 4 + (i & 3) + ((i >> 2) << 6);
        float* op = g_out1 + (size_t)(b * NP + n) * 512 + r0;
        *(float4*)&op[tx * 4]      = *(float4*)&acc[i][0];
        *(float4*)&op[tx * 4 + 64] = *(float4*)&acc[i][4];
    }
}

// ---------------- K5: gather + edge combine + bn1 partial stats ----------------
__global__ __launch_bounds__(128) void gather_kernel(const float* __restrict__ b1) {
    int b = blockIdx.y, nbase = blockIdx.x * 32;
    int o = threadIdx.x;
    float b1o = b1[o];
    float s = 0.f, ss = 0.f;
    for (int nn = 0; nn < 32; nn++) {
        int n = nbase + nn;
        const int* ip = g_idx + (b * NP + n) * KNN;
        const float* base = g_out1 + (size_t)(b * NP + n) * 512;
        float y0 = base[o] + b1o;
        float* hp = g_h + (size_t)(b * NP + n) * 3 * CH + o;
        #pragma unroll
        for (int j = 0; j < 3; j++) {
            int m0 = ip[j * 3 + 0], m1 = ip[j * 3 + 1], m2 = ip[j * 3 + 2];
            float z0 = g_out1[(size_t)(b * NP + m0) * 512 + 128 + o];
            float z1 = g_out1[(size_t)(b * NP + m1) * 512 + 256 + o];
            float z2 = g_out1[(size_t)(b * NP + m2) * 512 + 384 + o];
            float hv = y0 - z0 - z1 - z2;
            hp[j * CH] = hv;
            s += hv; ss = fmaf(hv, hv, ss);
        }
    }
    atomicAdd(&g_sum1[o], s);
    atomicAdd(&g_ss1[o], ss);
}

// ---------------- K6: finalize bn1 affine ----------------
__global__ void fin1_kernel(const float* __restrict__ g1, const float* __restrict__ beta1) {
    int o = threadIdx.x;
    float cnt = (float)(BATCH * NP * 3);
    float m = g_sum1[o] / cnt;
    float var = g_ss1[o] / cnt - m * m;
    var = fmaxf(var, 0.f);
    float is = rsqrtf(var + 1e-5f);
    float a = g1[o] * is;
    g_a1[o] = a;
    g_c1[o] = beta1[o] - m * a;
}

// ---------------- K7: conv2 GEMM with fused bn1-affine+relu on B load ----------------
__global__ __launch_bounds__(256) void gemm2_kernel(const float* __restrict__ b2) {
    __shared__ float As[TK][132];   // [k][o2]
    __shared__ float Bs[TK][132];   // [k][n]
    __shared__ float s_a1[CH], s_c1[CH];
    int b = blockIdx.y, n0 = blockIdx.x * 128;
    int t = threadIdx.x, tx = t & 15, ty = t >> 4;
    if (t < CH) { s_a1[t] = g_a1[t]; s_c1[t] = g_c1[t]; }
    __syncthreads();

    float acc[8][8];
    #pragma unroll
    for (int i = 0; i < 8; i++)
        #pragma unroll
        for (int j = 0; j < 8; j++) acc[i][j] = 0.f;

    for (int k0 = 0; k0 < 384; k0 += TK) {
        #pragma unroll
        for (int q = 0; q < 2; q++) {
            int qq = t + q * 256;
            int kc = qq >> 5, c4 = (qq & 31) << 2;
            *(float4*)&As[kc][c4] = *(const float4*)&g_w2t[(k0 + kc) * CH + c4];
        }
        #pragma unroll
        for (int q = 0; q < 2; q++) {
            int qq = t + q * 256;                 // 0..511
            int n_l = qq >> 2, kq = (qq & 3) << 2;
            float4 hv = *(const float4*)&g_h[(size_t)(b * NP + n0 + n_l) * 384 + k0 + kq];
            float vv[4] = {hv.x, hv.y, hv.z, hv.w};
            #pragma unroll
            for (int e = 0; e < 4; e++) {
                int c = (k0 + kq + e) & 127;
                Bs[kq + e][n_l] = fmaxf(fmaf(vv[e], s_a1[c], s_c1[c]), 0.f);
            }
        }
        __syncthreads();
        #pragma unroll
        for (int k = 0; k < TK; k++) {
            float fo[8], fn[8];
            *(float4*)(fo)     = *(float4*)&As[k][ty * 4];
            *(float4*)(fo + 4) = *(float4*)&As[k][ty * 4 + 64];
            *(float4*)(fn)     = *(float4*)&Bs[k][tx * 4];
            *(float4*)(fn + 4) = *(float4*)&Bs[k][tx * 4 + 64];
            #pragma unroll
            for (int i = 0; i < 8; i++)
                #pragma unroll
                for (int j = 0; j < 8; j++)
                    acc[i][j] = fmaf(fo[i], fn[j], acc[i][j]);
        }
        __syncthreads();
    }
    #pragma unroll
    for (int i = 0; i < 8; i++) {
        int o2 = ty * 4 + (i & 3) + ((i >> 2) << 6);
        float bb = b2[o2];
        float v0[4], v1[4];
        #pragma unroll
        for (int e = 0; e < 4; e++) { v0[e] = acc[i][e] + bb; v1[e] = acc[i][4 + e] + bb; }
        float* up = g_u + (size_t)(b * CH + o2) * NP + n0;
        *(float4*)&up[tx * 4]      = *(float4*)v0;
        *(float4*)&up[tx * 4 + 64] = *(float4*)v1;
    }
}

// ---------------- K8: bn2 stats + affine (block per channel) ----------------
__global__ __launch_bounds__(256) void stats2_kernel(const float* __restrict__ g2, const float* __restrict__ beta2) {
    int o2 = blockIdx.x;
    int t = threadIdx.x;
    float s = 0.f, ss = 0.f;
    for (int b = 0; b < BATCH; b++) {
        const float* up = g_u + (size_t)(b * CH + o2) * NP;
        for (int n = t; n < NP; n += 256) {
            float v = up[n];
            s += v; ss = fmaf(v, v, ss);
        }
    }
    __shared__ float rs[256], rss[256];
    rs[t] = s; rss[t] = ss;
    __syncthreads();
    for (int off = 128; off >= 1; off >>= 1) {
        if (t < off) { rs[t] += rs[t + off]; rss[t] += rss[t + off]; }
        __syncthreads();
    }
    if (t == 0) {
        float cnt = (float)(BATCH * NP);
        float m = rs[0] / cnt;
        float var = rss[0] / cnt - m * m;
        var = fmaxf(var, 0.f);
        float is = rsqrtf(var + 1e-5f);
        float a = g2[o2] * is;
        g_a2[o2] = a;
        g_c2[o2] = beta2[o2] - m * a;
    }
}

// ---------------- K9: final elementwise bn2+relu to output (float4) ----------------
__global__ void out_kernel(float* __restrict__ out) {
    int i = blockIdx.x * blockDim.x + threadIdx.x;    // float4 index
    if (i >= (BATCH * CH * NP) / 4) return;
    int o = (i >> 10) & 127;                          // (i*4 >> 12) & 127
    float a = g_a2[o], c = g_c2[o];
    float4 u = *((const float4*)g_u + i);
    float4 r;
    r.x = fmaxf(fmaf(u.x, a, c), 0.f);
    r.y = fmaxf(fmaf(u.y, a, c), 0.f);
    r.z = fmaxf(fmaf(u.z, a, c), 0.f);
    r.w = fmaxf(fmaf(u.w, a, c), 0.f);
    *((float4*)out + i) = r;
}

// ---------------- launch ----------------
extern "C" void kernel_launch(void* const* d_in, const int* in_sizes, int n_in,
                              void* d_out, int out_size) {
    const float* x     = (const float*)d_in[0];
    const float* w1    = (const float*)d_in[1];
    const float* b1    = (const float*)d_in[2];
    const float* g1    = (const float*)d_in[3];
    const float* beta1 = (const float*)d_in[4];
    const float* w2    = (const float*)d_in[5];
    const float* b2    = (const float*)d_in[6];
    const float* g2    = (const float*)d_in[7];
    const float* beta2 = (const float*)d_in[8];
    float* out = (float*)d_out;

    prep_kernel<<<256, 256>>>(w1, w2);
    sq_kernel<<<(BATCH * NP) / 256, 256>>>(x);
    pd_kernel<<<dim3(528, 1, BATCH), 256>>>(x);
    topk_kernel<<<(BATCH * NP) / 8, 256>>>();
    gemm1_kernel<<<dim3(4, 32, BATCH), 256>>>(x);
    gather_kernel<<<dim3(128, BATCH), 128>>>(b1);
    fin1_kernel<<<1, 128>>>(g1, beta1);
    gemm2_kernel<<<dim3(32, BATCH), 256>>>(b2);
    stats2_kernel<<<128, 256>>>(g2, beta2);
    out_kernel<<<(BATCH * CH * NP / 4 + 255) / 256, 256>>>(out);
}

// round 17
// speedup vs baseline: 1.5894x; 1.0412x over previous
#include <cuda_runtime.h>
#include <cstdint>

#define BATCH 8
#define CH    128
#define NP    4096
#define KNN   9
#define TK    16

#define NEG_INF __int_as_float(0xff800000)

// ---------------- packed f32x2 helpers (bit-exact: rn per component) ----------------
__device__ __forceinline__ unsigned long long pk2(float lo, float hi) {
    unsigned long long r;
    asm("mov.b64 %0, {%1, %2};" : "=l"(r) : "f"(lo), "f"(hi));
    return r;
}
__device__ __forceinline__ void upk2(unsigned long long v, float& lo, float& hi) {
    asm("mov.b64 {%0, %1}, %2;" : "=f"(lo), "=f"(hi) : "l"(v));
}
__device__ __forceinline__ void ffma2(unsigned long long& d, unsigned long long a, unsigned long long b) {
    asm("fma.rn.f32x2 %0, %1, %2, %0;" : "+l"(d) : "l"(a), "l"(b));
}
__device__ __forceinline__ void fadd2(unsigned long long& d, unsigned long long a) {
    asm("add.rn.f32x2 %0, %0, %1;" : "+l"(d) : "l"(a));
}

// ---------------- scratch (static __device__, no allocs) ----------------
__device__ float g_sq[BATCH * NP];
__device__ float g_pd[(size_t)BATCH * NP * NP];            // 512 MB
__device__ float g_tm[(size_t)BATCH * NP * 32];            // per-(row, col-tile) max, 4 MB
__device__ int   g_idx[BATCH * NP * KNN];
__device__ float g_wT[CH * 512];                           // [c][r] combined conv1 weights (transposed)
__device__ float g_w2t[384 * CH];                          // [kk][o2] conv2 weights (transposed, kk=j*128+c)
__device__ float g_out1[(size_t)BATCH * NP * 512];         // [b][n][r]: r<128 -> y0, r=128+128t+o -> z_t
__device__ float g_h[(size_t)BATCH * NP * 3 * CH];         // [b][n][j][c]
__device__ float g_u[(size_t)BATCH * CH * NP];             // [b][o][n] conv2 pre-BN
__device__ float g_sum1[CH], g_ss1[CH], g_a1[CH], g_c1[CH];
__device__ float g_a2[CH], g_c2[CH];

// ---------------- K0: weight prep + zero stats ----------------
__global__ void prep_kernel(const float* __restrict__ w1, const float* __restrict__ w2) {
    int i = blockIdx.x * blockDim.x + threadIdx.x;
    if (i < CH * 512) {
        int c = i / 512, r = i % 512;
        float v;
        if (r < CH) {
            int o = r;
            v = 0.f;
            #pragma unroll
            for (int t = 0; t < 3; t++)
                v += w1[o * 768 + c * 3 + t] + w1[o * 768 + (CH + c) * 3 + t];
        } else {
            int t = (r - CH) >> 7, o = (r - CH) & 127;
            v = w1[o * 768 + (CH + c) * 3 + t];
        }
        g_wT[i] = v;
    }
    if (i < 384 * CH) {
        int kk = i / CH, o2 = i % CH;
        int j = kk >> 7, c = kk & 127;
        g_w2t[i] = w2[o2 * 384 + c * 3 + j];
    }
    if (i < CH) { g_sum1[i] = 0.f; g_ss1[i] = 0.f; }
}

// ---------------- K1: squared norms (double accumulation of fp32 squares) ----------------
__global__ void sq_kernel(const float* __restrict__ x) {
    int i = blockIdx.x * blockDim.x + threadIdx.x;   // i = b*NP + n
    if (i >= BATCH * NP) return;
    int b = i >> 12, n = i & (NP - 1);
    const float* xp = x + (size_t)b * CH * NP + n;
    double s = 0.0;
    #pragma unroll 8
    for (int c = 0; c < CH; c++) {
        float v = xp[(size_t)c * NP];
        float p = __fmul_rn(v, v);        // match ref: fp32-rounded squares
        s += (double)p;                    // exact-ish sum
    }
    g_sq[i] = (float)s;
}

// ---------------- K2: pairwise pd (symmetric tiled sgemm, cascaded accumulation,
//                  register-prefetch pipeline, packed f32x2 FMA) + per-(row, tile) max ----------------
__global__ __launch_bounds__(256) void pd_kernel(const float* __restrict__ x) {
    // triangular block decode: only bi <= bj tiles exist
    int u = blockIdx.x, b = blockIdx.z;
    int bj = (int)((sqrtf(8.f * (float)u + 1.f) - 1.f) * 0.5f);
    while ((bj + 1) * (bj + 2) / 2 <= u) bj++;
    while (bj * (bj + 1) / 2 > u) bj--;
    int bi = u - bj * (bj + 1) / 2;

    __shared__ float As[TK][132];
    __shared__ float Bs[TK][132];
    __shared__ float Ms[128][17];     // mirror-row partial maxes [row][ty]
    const float* xb = x + (size_t)b * CH * NP;
    int n0 = bi * 128, m0 = bj * 128;
    int t = threadIdx.x, tx = t & 15, ty = t >> 4;

    // per-thread load coordinates (2 float4 loads per chunk)
    int kc0 = t >> 5,        c40 = (t & 31) << 2;
    int kc1 = (t + 256) >> 5, c41 = ((t + 256) & 31) << 2;

    unsigned long long pacc[8][4];
    #pragma unroll
    for (int i = 0; i < 8; i++)
        #pragma unroll
        for (int jp = 0; jp < 4; jp++) pacc[i][jp] = 0ULL;

    // prefetch chunk 0 into registers
    float4 ra0 = *(const float4*)&xb[(size_t)kc0 * NP + n0 + c40];
    float4 rb0 = *(const float4*)&xb[(size_t)kc0 * NP + m0 + c40];
    float4 ra1 = *(const float4*)&xb[(size_t)kc1 * NP + n0 + c41];
    float4 rb1 = *(const float4*)&xb[(size_t)kc1 * NP + m0 + c41];

    for (int k0 = 0; k0 < CH; k0 += TK) {
        __syncthreads();                 // smem free (previous compute done)
        *(float4*)&As[kc0][c40] = ra0;
        *(float4*)&Bs[kc0][c40] = rb0;
        *(float4*)&As[kc1][c41] = ra1;
        *(float4*)&Bs[kc1][c41] = rb1;
        __syncthreads();
        if (k0 + TK < CH) {              // prefetch next chunk (overlaps compute)
            ra0 = *(const float4*)&xb[(size_t)(k0 + TK + kc0) * NP + n0 + c40];
            rb0 = *(const float4*)&xb[(size_t)(k0 + TK + kc0) * NP + m0 + c40];
            ra1 = *(const float4*)&xb[(size_t)(k0 + TK + kc1) * NP + n0 + c41];
            rb1 = *(const float4*)&xb[(size_t)(k0 + TK + kc1) * NP + m0 + c41];
        }
        // fresh chunk accumulators: keeps partial-sum magnitudes small
        unsigned long long pC[8][4];
        #pragma unroll
        for (int i = 0; i < 8; i++)
            #pragma unroll
            for (int jp = 0; jp < 4; jp++) pC[i][jp] = 0ULL;
        #pragma unroll
        for (int k = 0; k < TK; k++) {
            float a[8], bb[8];
            *(float4*)(a)      = *(float4*)&As[k][ty * 4];
            *(float4*)(a + 4)  = *(float4*)&As[k][ty * 4 + 64];
            *(float4*)(bb)     = *(float4*)&Bs[k][tx * 4];
            *(float4*)(bb + 4) = *(float4*)&Bs[k][tx * 4 + 64];
            unsigned long long pb[4];
            #pragma unroll
            for (int jp = 0; jp < 4; jp++) pb[jp] = pk2(bb[2 * jp], bb[2 * jp + 1]);
            #pragma unroll
            for (int i = 0; i < 8; i++) {
                unsigned long long pa = pk2(a[i], a[i]);
                #pragma unroll
                for (int jp = 0; jp < 4; jp++) ffma2(pC[i][jp], pa, pb[jp]);
            }
        }
        #pragma unroll
        for (int i = 0; i < 8; i++)
            #pragma unroll
            for (int jp = 0; jp < 4; jp++) fadd2(pacc[i][jp], pC[i][jp]);
    }

    // unpack to scalar accumulators for the (unchanged) epilogue
    float acc[8][8];
    #pragma unroll
    for (int i = 0; i < 8; i++)
        #pragma unroll
        for (int jp = 0; jp < 4; jp++) upk2(pacc[i][jp], acc[i][2 * jp], acc[i][2 * jp + 1]);

    float sqn[8], sqm[8];
    #pragma unroll
    for (int i = 0; i < 8; i++)
        sqn[i] = g_sq[b * NP + n0 + ty * 4 + (i & 3) + ((i >> 2) << 6)];
    #pragma unroll
    for (int j = 0; j < 8; j++)
        sqm[j] = g_sq[b * NP + m0 + tx * 4 + (j & 3) + ((j >> 2) << 6)];

    float* pdb = g_pd + (size_t)b * NP * NP;
    // forward stores (rows n, coalesced float4) + per-row tile max
    #pragma unroll
    for (int i = 0; i < 8; i++) {
        int n = n0 + ty * 4 + (i & 3) + ((i >> 2) << 6);
        float v0[4], v1[4];
        #pragma unroll
        for (int e = 0; e < 4; e++) {
            float t0 = __fsub_rn(__fmul_rn(2.f, acc[i][e]),     sqn[i]); v0[e] = __fsub_rn(t0, sqm[e]);
            float t1 = __fsub_rn(__fmul_rn(2.f, acc[i][4 + e]), sqn[i]); v1[e] = __fsub_rn(t1, sqm[4 + e]);
        }
        *(float4*)&pdb[(size_t)n * NP + m0 + tx * 4]      = *(float4*)v0;
        *(float4*)&pdb[(size_t)n * NP + m0 + tx * 4 + 64] = *(float4*)v1;
        // row max over this thread's 8 cols, then across the 16 tx lanes (same half-warp)
        float rmax = fmaxf(fmaxf(fmaxf(v0[0], v0[1]), fmaxf(v0[2], v0[3])),
                           fmaxf(fmaxf(v1[0], v1[1]), fmaxf(v1[2], v1[3])));
        #pragma unroll
        for (int off = 8; off >= 1; off >>= 1)
            rmax = fmaxf(rmax, __shfl_xor_sync(0xffffffffu, rmax, off));
        if (tx == 0) g_tm[(size_t)(b * NP + n) * 32 + bj] = rmax;
    }
    // mirror stores (rows m): j-outer, i-inner, emit two float4 per m-row + tile max via smem
    if (bi != bj) {
        __syncthreads();                  // Ms reuses smem timeline; ensure prior phase done
        #pragma unroll
        for (int j = 0; j < 8; j++) {
            int jj = tx * 4 + (j & 3) + ((j >> 2) << 6);    // row-local index 0..127
            int m = m0 + jj;
            float w0[4], w1v[4];
            #pragma unroll
            for (int i = 0; i < 4; i++) {
                float t2 = __fsub_rn(__fmul_rn(2.f, acc[i][j]), sqm[j]);   // reference order for row m
                w0[i] = __fsub_rn(t2, sqn[i]);                              // n = n0+ty*4+i (consecutive)
            }
            #pragma unroll
            for (int i = 4; i < 8; i++) {
                float t2 = __fsub_rn(__fmul_rn(2.f, acc[i][j]), sqm[j]);
                w1v[i - 4] = __fsub_rn(t2, sqn[i]);                         // n = n0+ty*4+64+(i-4)
            }
            *(float4*)&pdb[(size_t)m * NP + n0 + ty * 4]      = *(float4*)w0;
            *(float4*)&pdb[(size_t)m * NP + n0 + ty * 4 + 64] = *(float4*)w1v;
            float mm = fmaxf(fmaxf(fmaxf(w0[0], w0[1]), fmaxf(w0[2], w0[3])),
                             fmaxf(fmaxf(w1v[0], w1v[1]), fmaxf(w1v[2], w1v[3])));
            Ms[jj][ty] = mm;
        }
        __syncthreads();
        if (t < 128) {
            float r = Ms[t][0];
            #pragma unroll
            for (int q = 1; q < 16; q++) r = fmaxf(r, Ms[t][q]);
            g_tm[(size_t)(b * NP + m0 + t) * 32 + bi] = r;
        }
    }
}

// ---------------- K3: top-9 per row via exact tile-max threshold (jax top_k semantics) ----------------
__global__ __launch_bounds__(256) void topk_kernel() {
    int warp = threadIdx.x >> 5, lane = threadIdx.x & 31;
    int row = blockIdx.x * 8 + warp;                 // row = b*NP + n
    const float4* pr = (const float4*)(g_pd + (size_t)row * NP);
    float tm = g_tm[(size_t)row * 32 + lane];        // lane's tile max

    // v9 = 9th largest of the 32 tile maxima (multiset order, 9 extraction rounds)
    float rem = tm, v9 = NEG_INF;
    #pragma unroll
    for (int r = 0; r < KNN; r++) {
        float m = rem;
        #pragma unroll
        for (int off = 16; off >= 1; off >>= 1)
            m = fmaxf(m, __shfl_xor_sync(0xffffffffu, m, off));
        v9 = m;
        unsigned msk = __ballot_sync(0xffffffffu, rem == m);
        int src = __ffs((int)msk) - 1;               // remove exactly one holder per round
        if (lane == src) rem = NEG_INF;
    }

    float v[KNN]; int id[KNN];
    #pragma unroll
    for (int s = 0; s < KNN; s++) { v[s] = NEG_INF; id[s] = 0x7fffffff; }

    for (int tt = 0; tt < 32; tt++) {
        float tmt = __shfl_sync(0xffffffffu, tm, tt);
        if (tmt >= v9) {                             // warp-uniform tile skip
            float4 p = pr[tt * 32 + lane];           // tile tt: 128 floats, one float4/lane
            float mx = fmaxf(fmaxf(p.x, p.y), fmaxf(p.z, p.w));
            if (mx >= v9) {
                int mbase = (tt * 32 + lane) * 4;
                float pe[4] = {p.x, p.y, p.z, p.w};
                #pragma unroll
                for (int e = 0; e < 4; e++) {
                    float cv = pe[e];
                    if (cv >= v9) {
                        int ci = mbase + e;
                        #pragma unroll
                        for (int s = 0; s < KNN; s++) {
                            bool take = (cv > v[s]);
                            float tv = take ? v[s] : cv;  int ti = take ? id[s] : ci;
                            v[s]  = take ? cv : v[s];     id[s] = take ? ci : id[s];
                            cv = tv; ci = ti;
                        }
                    }
                }
            }
        }
    }

    int* outp = g_idx + row * KNN;
    #pragma unroll
    for (int r = 0; r < KNN; r++) {
        float cv = v[0]; int ci = id[0];
        #pragma unroll
        for (int s = 1; s < KNN; s++) {
            bool better = (v[s] > cv) || (v[s] == cv && id[s] < ci);
            cv = better ? v[s] : cv; ci = better ? id[s] : ci;
        }
        #pragma unroll
        for (int off = 16; off >= 1; off >>= 1) {
            float wv = __shfl_xor_sync(0xffffffffu, cv, off);
            int   wi = __shfl_xor_sync(0xffffffffu, ci, off);
            bool better = (wv > cv) || (wv == cv && wi < ci);
            cv = better ? wv : cv; ci = better ? wi : ci;
        }
        if (lane == 0) outp[r] = ci;
        #pragma unroll
        for (int s = 0; s < KNN; s++)
            if (id[s] == ci) { v[s] = NEG_INF; id[s] = 0x7fffffff; }
    }
}

// ---------------- K4: combined conv1 GEMM (packed f32x2): out1[b][n][r] = W[r][:] . x[:, n] ----------------
__global__ __launch_bounds__(256) void gemm1_kernel(const float* __restrict__ x) {
    __shared__ float As[TK][132];   // [k][r]
    __shared__ float Bs[TK][132];   // [k][n]
    int b = blockIdx.z, r0 = blockIdx.x * 128, n0 = blockIdx.y * 128;
    const float* xb = x + (size_t)b * CH * NP;
    int t = threadIdx.x, tx = t & 15, ty = t >> 4;

    unsigned long long pacc[8][4];
    #pragma unroll
    for (int i = 0; i < 8; i++)
        #pragma unroll
        for (int jp = 0; jp < 4; jp++) pacc[i][jp] = 0ULL;

    for (int k0 = 0; k0 < CH; k0 += TK) {
        #pragma unroll
        for (int q = 0; q < 2; q++) {
            int qq = t + q * 256;
            int kc = qq >> 5, c4 = (qq & 31) << 2;
            *(float4*)&As[kc][c4] = *(const float4*)&g_wT[(k0 + kc) * 512 + r0 + c4];
            *(float4*)&Bs[kc][c4] = *(const float4*)&xb[(size_t)(k0 + kc) * NP + n0 + c4];
        }
        __syncthreads();
        #pragma unroll
        for (int k = 0; k < TK; k++) {
            float fr[8], fn[8];
            *(float4*)(fr)     = *(float4*)&As[k][tx * 4];
            *(float4*)(fr + 4) = *(float4*)&As[k][tx * 4 + 64];
            *(float4*)(fn)     = *(float4*)&Bs[k][ty * 4];
            *(float4*)(fn + 4) = *(float4*)&Bs[k][ty * 4 + 64];
            unsigned long long pb[4];
            #pragma unroll
            for (int jp = 0; jp < 4; jp++) pb[jp] = pk2(fr[2 * jp], fr[2 * jp + 1]);
            #pragma unroll
            for (int i = 0; i < 8; i++) {
                unsigned long long pa = pk2(fn[i], fn[i]);
                #pragma unroll
                for (int jp = 0; jp < 4; jp++) ffma2(pacc[i][jp], pa, pb[jp]);
            }
        }
        __syncthreads();
    }
    float acc[8][8];
    #pragma unroll
    for (int i = 0; i < 8; i++)
        #pragma unroll
        for (int jp = 0; jp < 4; jp++) upk2(pacc[i][jp], acc[i][2 * jp], acc[i][2 * jp + 1]);
    #pragma unroll
    for (int i = 0; i < 8; i++) {
        int n = n0 + ty * 4 + (i & 3) + ((i >> 2) << 6);
        float* op = g_out1 + (size_t)(b * NP + n) * 512 + r0;
        *(float4*)&op[tx * 4]      = *(float4*)&acc[i][0];
        *(float4*)&op[tx * 4 + 64] = *(float4*)&acc[i][4];
    }
}

// ---------------- K5: gather + edge combine + bn1 partial stats ----------------
__global__ __launch_bounds__(128) void gather_kernel(const float* __restrict__ b1) {
    int b = blockIdx.y, nbase = blockIdx.x * 32;
    int o = threadIdx.x;
    float b1o = b1[o];
    float s = 0.f, ss = 0.f;
    for (int nn = 0; nn < 32; nn++) {
        int n = nbase + nn;
        const int* ip = g_idx + (b * NP + n) * KNN;
        const float* base = g_out1 + (size_t)(b * NP + n) * 512;
        float y0 = base[o] + b1o;
        float* hp = g_h + (size_t)(b * NP + n) * 3 * CH + o;
        #pragma unroll
        for (int j = 0; j < 3; j++) {
            int m0 = ip[j * 3 + 0], m1 = ip[j * 3 + 1], m2 = ip[j * 3 + 2];
            float z0 = g_out1[(size_t)(b * NP + m0) * 512 + 128 + o];
            float z1 = g_out1[(size_t)(b * NP + m1) * 512 + 256 + o];
            float z2 = g_out1[(size_t)(b * NP + m2) * 512 + 384 + o];
            float hv = y0 - z0 - z1 - z2;
            hp[j * CH] = hv;
            s += hv; ss = fmaf(hv, hv, ss);
        }
    }
    atomicAdd(&g_sum1[o], s);
    atomicAdd(&g_ss1[o], ss);
}

// ---------------- K6: finalize bn1 affine ----------------
__global__ void fin1_kernel(const float* __restrict__ g1, const float* __restrict__ beta1) {
    int o = threadIdx.x;
    float cnt = (float)(BATCH * NP * 3);
    float m = g_sum1[o] / cnt;
    float var = g_ss1[o] / cnt - m * m;
    var = fmaxf(var, 0.f);
    float is = rsqrtf(var + 1e-5f);
    float a = g1[o] * is;
    g_a1[o] = a;
    g_c1[o] = beta1[o] - m * a;
}

// ---------------- K7: conv2 GEMM (packed f32x2) with fused bn1-affine+relu on B load ----------------
__global__ __launch_bounds__(256) void gemm2_kernel(const float* __restrict__ b2) {
    __shared__ float As[TK][132];   // [k][o2]
    __shared__ float Bs[TK][132];   // [k][n]
    __shared__ float s_a1[CH], s_c1[CH];
    int b = blockIdx.y, n0 = blockIdx.x * 128;
    int t = threadIdx.x, tx = t & 15, ty = t >> 4;
    if (t < CH) { s_a1[t] = g_a1[t]; s_c1[t] = g_c1[t]; }
    __syncthreads();

    unsigned long long pacc[8][4];
    #pragma unroll
    for (int i = 0; i < 8; i++)
        #pragma unroll
        for (int jp = 0; jp < 4; jp++) pacc[i][jp] = 0ULL;

    for (int k0 = 0; k0 < 384; k0 += TK) {
        #pragma unroll
        for (int q = 0; q < 2; q++) {
            int qq = t + q * 256;
            int kc = qq >> 5, c4 = (qq & 31) << 2;
            *(float4*)&As[kc][c4] = *(const float4*)&g_w2t[(k0 + kc) * CH + c4];
        }
        #pragma unroll
        for (int q = 0; q < 2; q++) {
            int qq = t + q * 256;                 // 0..511
            int n_l = qq >> 2, kq = (qq & 3) << 2;
            float4 hv = *(const float4*)&g_h[(size_t)(b * NP + n0 + n_l) * 384 + k0 + kq];
            float vv[4] = {hv.x, hv.y, hv.z, hv.w};
            #pragma unroll
            for (int e = 0; e < 4; e++) {
                int c = (k0 + kq + e) & 127;
                Bs[kq + e][n_l] = fmaxf(fmaf(vv[e], s_a1[c], s_c1[c]), 0.f);
            }
        }
        __syncthreads();
        #pragma unroll
        for (int k = 0; k < TK; k++) {
            float fo[8], fn[8];
            *(float4*)(fo)     = *(float4*)&As[k][ty * 4];
            *(float4*)(fo + 4) = *(float4*)&As[k][ty * 4 + 64];
            *(float4*)(fn)     = *(float4*)&Bs[k][tx * 4];
            *(float4*)(fn + 4) = *(float4*)&Bs[k][tx * 4 + 64];
            unsigned long long pb[4];
            #pragma unroll
            for (int jp = 0; jp < 4; jp++) pb[jp] = pk2(fn[2 * jp], fn[2 * jp + 1]);
            #pragma unroll
            for (int i = 0; i < 8; i++) {
                unsigned long long pa = pk2(fo[i], fo[i]);
                #pragma unroll
                for (int jp = 0; jp < 4; jp++) ffma2(pacc[i][jp], pa, pb[jp]);
            }
        }
        __syncthreads();
    }
    float acc[8][8];
    #pragma unroll
    for (int i = 0; i < 8; i++)
        #pragma unroll
        for (int jp = 0; jp < 4; jp++) upk2(pacc[i][jp], acc[i][2 * jp], acc[i][2 * jp + 1]);
    #pragma unroll
    for (int i = 0; i < 8; i++) {
        int o2 = ty * 4 + (i & 3) + ((i >> 2) << 6);
        float bb = b2[o2];
        float v0[4], v1[4];
        #pragma unroll
        for (int e = 0; e < 4; e++) { v0[e] = acc[i][e] + bb; v1[e] = acc[i][4 + e] + bb; }
        float* up = g_u + (size_t)(b * CH + o2) * NP + n0;
        *(float4*)&up[tx * 4]      = *(float4*)v0;
        *(float4*)&up[tx * 4 + 64] = *(float4*)v1;
    }
}

// ---------------- K8: bn2 stats + affine (block per channel) ----------------
__global__ __launch_bounds__(256) void stats2_kernel(const float* __restrict__ g2, const float* __restrict__ beta2) {
    int o2 = blockIdx.x;
    int t = threadIdx.x;
    float s = 0.f, ss = 0.f;
    for (int b = 0; b < BATCH; b++) {
        const float* up = g_u + (size_t)(b * CH + o2) * NP;
        for (int n = t; n < NP; n += 256) {
            float v = up[n];
            s += v; ss = fmaf(v, v, ss);
        }
    }
    __shared__ float rs[256], rss[256];
    rs[t] = s; rss[t] = ss;
    __syncthreads();
    for (int off = 128; off >= 1; off >>= 1) {
        if (t < off) { rs[t] += rs[t + off]; rss[t] += rss[t + off]; }
        __syncthreads();
    }
    if (t == 0) {
        float cnt = (float)(BATCH * NP);
        float m = rs[0] / cnt;
        float var = rss[0] / cnt - m * m;
        var = fmaxf(var, 0.f);
        float is = rsqrtf(var + 1e-5f);
        float a = g2[o2] * is;
        g_a2[o2] = a;
        g_c2[o2] = beta2[o2] - m * a;
    }
}

// ---------------- K9: final elementwise bn2+relu to output (float4) ----------------
__global__ void out_kernel(float* __restrict__ out) {
    int i = blockIdx.x * blockDim.x + threadIdx.x;    // float4 index
    if (i >= (BATCH * CH * NP) / 4) return;
    int o = (i >> 10) & 127;                          // (i*4 >> 12) & 127
    float a = g_a2[o], c = g_c2[o];
    float4 u = *((const float4*)g_u + i);
    float4 r;
    r.x = fmaxf(fmaf(u.x, a, c), 0.f);
    r.y = fmaxf(fmaf(u.y, a, c), 0.f);
    r.z = fmaxf(fmaf(u.z, a, c), 0.f);
    r.w = fmaxf(fmaf(u.w, a, c), 0.f);
    *((float4*)out + i) = r;
}

// ---------------- launch ----------------
extern "C" void kernel_launch(void* const* d_in, const int* in_sizes, int n_in,
                              void* d_out, int out_size) {
    const float* x     = (const float*)d_in[0];
    const float* w1    = (const float*)d_in[1];
    const float* b1    = (const float*)d_in[2];
    const float* g1    = (const float*)d_in[3];
    const float* beta1 = (const float*)d_in[4];
    const float* w2    = (const float*)d_in[5];
    const float* b2    = (const float*)d_in[6];
    const float* g2    = (const float*)d_in[7];
    const float* beta2 = (const float*)d_in[8];
    float* out = (float*)d_out;

    prep_kernel<<<256, 256>>>(w1, w2);
    sq_kernel<<<(BATCH * NP) / 256, 256>>>(x);
    pd_kernel<<<dim3(528, 1, BATCH), 256>>>(x);
    topk_kernel<<<(BATCH * NP) / 8, 256>>>();
    gemm1_kernel<<<dim3(4, 32, BATCH), 256>>>(x);
    gather_kernel<<<dim3(128, BATCH), 128>>>(b1);
    fin1_kernel<<<1, 128>>>(g1, beta1);
    gemm2_kernel<<<dim3(32, BATCH), 256>>>(b2);
    stats2_kernel<<<128, 256>>>(g2, beta2);
    out_kernel<<<(BATCH * CH * NP / 4 + 255) / 256, 256>>>(out);
}